// round 11
// baseline (speedup 1.0000x reference)
#include <cuda_runtime.h>
#include <math.h>

#define NROWS 16384
#define NCOLS 1024
#define F4_PER_ROW (NCOLS / 4)        // 256
#define BLOCKS 296                    // 2 CTAs/SM x 148 SMs
#define THREADS 512                   // 1024 thr/SM -> 64-reg budget per thread
#define NBUCKETS 8

__device__ float g_colsum[NBUCKETS][NCOLS];   // zero-init at module load
__device__ float g_sqsum;
__device__ unsigned int g_count;

__device__ __forceinline__ float warp_reduce_sum(float v) {
    #pragma unroll
    for (int off = 16; off > 0; off >>= 1)
        v += __shfl_xor_sync(0xFFFFFFFFu, v, off);
    return v;
}

__device__ __forceinline__ void acc(const float4& v, float4& cs, float& sq) {
    cs.x += v.x; cs.y += v.y; cs.z += v.z; cs.w += v.w;
    sq = fmaf(v.x, v.x, sq); sq = fmaf(v.y, v.y, sq);
    sq = fmaf(v.z, v.z, sq); sq = fmaf(v.w, v.w, sq);
}

__global__ void __launch_bounds__(THREADS, 2)
l2_fused_kernel(const float* __restrict__ feats, float* __restrict__ out) {
    const int t = threadIdx.x;
    const int bid = blockIdx.x;
    const int sub = t >> 8;            // 0..1: which of 2 concurrent rows
    const int cg  = t & 255;           // float4 column group
    const float4* __restrict__ f4 = reinterpret_cast<const float4*>(feats);

    // Balanced contiguous stripes: rpb=55, first 104 blocks get 56.
    const int rpb  = NROWS / BLOCKS;           // 55
    const int rem  = NROWS % BLOCKS;           // 104
    const int row0 = bid * rpb + (bid < rem ? bid : rem);
    const int nrows = rpb + (bid < rem ? 1 : 0);

    float4 cs0 = make_float4(0.f, 0.f, 0.f, 0.f);
    float4 cs1 = make_float4(0.f, 0.f, 0.f, 0.f);
    float sq0 = 0.f, sq1 = 0.f;

    // Thread covers rows row0+sub, +2, +4, ...  Main loop: 8 loads issued
    // back-to-back (8 independent LDG.128.CG in flight) before consumption.
    const float4* p = f4 + (size_t)(row0 + sub) * F4_PER_ROW + cg;
    int r = sub;
    for (; r + 14 < nrows; r += 16) {
        float4 v0 = __ldcg(p + 0 * 2 * F4_PER_ROW);
        float4 v1 = __ldcg(p + 1 * 2 * F4_PER_ROW);
        float4 v2 = __ldcg(p + 2 * 2 * F4_PER_ROW);
        float4 v3 = __ldcg(p + 3 * 2 * F4_PER_ROW);
        float4 v4 = __ldcg(p + 4 * 2 * F4_PER_ROW);
        float4 v5 = __ldcg(p + 5 * 2 * F4_PER_ROW);
        float4 v6 = __ldcg(p + 6 * 2 * F4_PER_ROW);
        float4 v7 = __ldcg(p + 7 * 2 * F4_PER_ROW);
        p += 16 * F4_PER_ROW;
        acc(v0, cs0, sq0); acc(v1, cs1, sq1);
        acc(v2, cs0, sq0); acc(v3, cs1, sq1);
        acc(v4, cs0, sq0); acc(v5, cs1, sq1);
        acc(v6, cs0, sq0); acc(v7, cs1, sq1);
    }
    for (; r < nrows; r += 2) {
        float4 v = __ldcg(p);
        p += 2 * F4_PER_ROW;
        acc(v, cs0, sq0);
    }
    cs0.x += cs1.x; cs0.y += cs1.y; cs0.z += cs1.z; cs0.w += cs1.w;
    float sq = sq0 + sq1;

    // Combine the 2 subrow partials per column group in SMEM; only sub==0
    // (warps 0-7) issues the 1024 global atomics per block.
    __shared__ float4 s_part[256];             // 4 KB
    __shared__ float s_warp[THREADS / 32];
    __shared__ int s_last;

    if (sub != 0) s_part[cg] = cs0;

    float wsum = warp_reduce_sum(sq);
    int lane = t & 31, wid = t >> 5;
    if (lane == 0) s_warp[wid] = wsum;
    __syncthreads();

    if (sub == 0) {
        float4 a = s_part[cg];
        cs0.x += a.x; cs0.y += a.y; cs0.z += a.z; cs0.w += a.w;
        float* bucket = g_colsum[bid & (NBUCKETS - 1)];
        atomicAdd(&bucket[4 * cg + 0], cs0.x);
        atomicAdd(&bucket[4 * cg + 1], cs0.y);
        atomicAdd(&bucket[4 * cg + 2], cs0.z);
        atomicAdd(&bucket[4 * cg + 3], cs0.w);
    }
    if (wid == 0) {
        float v = (lane < THREADS / 32) ? s_warp[lane] : 0.f;
        v = warp_reduce_sum(v);
        if (lane == 0) atomicAdd(&g_sqsum, v);
    }

    // Last-block vote (fence makes our atomics globally visible first).
    __threadfence();
    if (t == 0) {
        unsigned int prev = atomicAdd(&g_count, 1u);
        s_last = (prev == BLOCKS - 1u) ? 1 : 0;
    }
    __syncthreads();

    if (s_last) {
        // Fold 8 buckets, square, reset state for the next graph replay.
        float d = 0.f;
        #pragma unroll
        for (int i = t; i < NCOLS; i += THREADS) {
            float c = 0.f;
            #pragma unroll
            for (int b = 0; b < NBUCKETS; b++) {
                c += __ldcg(&g_colsum[b][i]);
                g_colsum[b][i] = 0.f;
            }
            d = fmaf(c, c, d);
        }
        float wd = warp_reduce_sum(d);
        if (lane == 0) s_warp[wid] = wd;
        __syncthreads();
        if (wid == 0) {
            float v = (lane < THREADS / 32) ? s_warp[lane] : 0.f;
            v = warp_reduce_sum(v);
            if (lane == 0) {
                double sqtot = (double)__ldcg(&g_sqsum);
                double dot = (double)v;
                double pair_sum = (double)NROWS * sqtot - dot;
                double count = (double)NROWS * (NROWS - 1) / 2.0;
                out[0] = (float)exp(-pair_sum / count);
                g_sqsum = 0.f;
                g_count = 0u;
            }
        }
    }
}

extern "C" void kernel_launch(void* const* d_in, const int* in_sizes, int n_in,
                              void* d_out, int out_size) {
    const float* feats = (const float*)d_in[0];
    float* out = (float*)d_out;
    l2_fused_kernel<<<BLOCKS, THREADS>>>(feats, out);
}